// round 1
// baseline (speedup 1.0000x reference)
#include <cuda_runtime.h>

#define Bn 4
#define Tn 512
#define Dn 1024
#define Hn 16
#define HSn 64
#define Ln 8
#define Vn 32000
#define Mn (Bn*Tn)       // 2048
#define FFn (4*Dn)       // 4096
#define BHn (Bn*Hn)      // 64

// ---------------- scratch (device globals: no allocation allowed) ----------
__device__ float g_h[Mn*Dn];
__device__ float g_y[Mn*Dn];
__device__ float g_q[Mn*Dn];
__device__ float g_k[Mn*Dn];
__device__ float g_v[Mn*Dn];
__device__ float g_o[Mn*Dn];
__device__ float g_a[Mn*FFn];
__device__ float g_s[(size_t)BHn*Tn*Tn];

// ---------------- reductions ----------------
__device__ __forceinline__ float warpSum(float v){
#pragma unroll
    for (int o = 16; o > 0; o >>= 1) v += __shfl_down_sync(0xffffffffu, v, o);
    return v;
}
__device__ __forceinline__ float warpMax(float v){
#pragma unroll
    for (int o = 16; o > 0; o >>= 1) v = fmaxf(v, __shfl_down_sync(0xffffffffu, v, o));
    return v;
}
__device__ __forceinline__ float blockSum(float v, float* sh){
    int lane = threadIdx.x & 31, w = threadIdx.x >> 5;
    v = warpSum(v);
    __syncthreads();
    if (lane == 0) sh[w] = v;
    __syncthreads();
    int nw = blockDim.x >> 5;
    v = (threadIdx.x < (unsigned)nw) ? sh[threadIdx.x] : 0.f;
    if (w == 0) v = warpSum(v);
    if (threadIdx.x == 0) sh[0] = v;
    __syncthreads();
    return sh[0];
}
__device__ __forceinline__ float blockMax(float v, float* sh){
    int lane = threadIdx.x & 31, w = threadIdx.x >> 5;
    v = warpMax(v);
    __syncthreads();
    if (lane == 0) sh[w] = v;
    __syncthreads();
    int nw = blockDim.x >> 5;
    v = (threadIdx.x < (unsigned)nw) ? sh[threadIdx.x] : -3.0e38f;
    if (w == 0) v = warpMax(v);
    if (threadIdx.x == 0) sh[0] = v;
    __syncthreads();
    return sh[0];
}

// ---------------- embedding: h = char_emb[x] + pos_emb ----------------
__global__ void embed_k(const int* __restrict__ x, const float* __restrict__ ce,
                        const float* __restrict__ pe){
    int idx = blockIdx.x * blockDim.x + threadIdx.x;  // over Mn*Dn
    int d  = idx & (Dn - 1);
    int mt = idx >> 10;           // row in [0, Mn)
    int t  = mt & (Tn - 1);
    g_h[idx] = ce[(size_t)x[mt] * Dn + d] + pe[t * Dn + d];
}

// ---------------- layernorm: out = (x-mean)*rsqrt(var+eps)*s + b ------------
__global__ __launch_bounds__(256) void ln_k(const float* __restrict__ in,
                                            float* __restrict__ out,
                                            const float* __restrict__ gs,
                                            const float* __restrict__ gb){
    __shared__ float sh[32];
    int row = blockIdx.x;
    const float* xr = in + (size_t)row * Dn;
    float s = 0.f, sq = 0.f;
    for (int i = threadIdx.x; i < Dn; i += 256){ float v = xr[i]; s += v; sq += v * v; }
    s  = blockSum(s, sh);
    sq = blockSum(sq, sh);
    float mean = s * (1.f / Dn);
    float var  = sq * (1.f / Dn) - mean * mean;
    float r = rsqrtf(var + 1e-5f);
    float* orow = out + (size_t)row * Dn;
    for (int i = threadIdx.x; i < Dn; i += 256)
        orow[i] = (xr[i] - mean) * r * gs[i] + gb[i];
}

// ---------------- generic SGEMM: C = A[M,K] @ B[K,N] (+res) (+bias) (relu) --
// Requires: M%128==0, N%128==0, K%8==0. All shapes here satisfy that.
__global__ __launch_bounds__(256) void sgemm_k(const float* __restrict__ A,
                                               const float* __restrict__ Bw,
                                               const float* __restrict__ bias,
                                               const float* __restrict__ res,
                                               float* __restrict__ C,
                                               int M, int N, int K, int relu){
    __shared__ float As[8][128];
    __shared__ float Bs[8][128];
    const int tid = threadIdx.x;
    const int bm = blockIdx.y * 128, bn = blockIdx.x * 128;
    const int arow = tid >> 1, acol = (tid & 1) * 4;
    const int brow = tid >> 5, bcol = (tid & 31) * 4;
    const int tx = tid & 15, ty = tid >> 4;
    float acc[8][8];
#pragma unroll
    for (int i = 0; i < 8; i++)
#pragma unroll
        for (int j = 0; j < 8; j++) acc[i][j] = 0.f;

    const float* Ap = A + (size_t)(bm + arow) * K + acol;
    const float* Bp = Bw + (size_t)brow * N + bn + bcol;

    for (int k0 = 0; k0 < K; k0 += 8){
        float4 av = *(const float4*)(Ap + k0);
        float4 bv = *(const float4*)(Bp + (size_t)k0 * N);
        As[acol + 0][arow] = av.x;
        As[acol + 1][arow] = av.y;
        As[acol + 2][arow] = av.z;
        As[acol + 3][arow] = av.w;
        *(float4*)&Bs[brow][bcol] = bv;
        __syncthreads();
#pragma unroll
        for (int kk = 0; kk < 8; kk++){
            float a[8], b[8];
            *(float4*)&a[0] = *(const float4*)&As[kk][ty * 8];
            *(float4*)&a[4] = *(const float4*)&As[kk][ty * 8 + 4];
            *(float4*)&b[0] = *(const float4*)&Bs[kk][tx * 8];
            *(float4*)&b[4] = *(const float4*)&Bs[kk][tx * 8 + 4];
#pragma unroll
            for (int i = 0; i < 8; i++)
#pragma unroll
                for (int j = 0; j < 8; j++)
                    acc[i][j] += a[i] * b[j];
        }
        __syncthreads();
    }

    const int crow = bm + ty * 8, ccol = bn + tx * 8;
#pragma unroll
    for (int i = 0; i < 8; i++){
        size_t off = (size_t)(crow + i) * N + ccol;
#pragma unroll
        for (int jj = 0; jj < 8; jj += 4){
            float4 v;
            v.x = acc[i][jj + 0]; v.y = acc[i][jj + 1];
            v.z = acc[i][jj + 2]; v.w = acc[i][jj + 3];
            if (res){
                float4 rr = *(const float4*)(res + off + jj);
                v.x += rr.x; v.y += rr.y; v.z += rr.z; v.w += rr.w;
            }
            if (bias){
                v.x += bias[ccol + jj + 0]; v.y += bias[ccol + jj + 1];
                v.z += bias[ccol + jj + 2]; v.w += bias[ccol + jj + 3];
            }
            if (relu){
                v.x = fmaxf(v.x, 0.f); v.y = fmaxf(v.y, 0.f);
                v.z = fmaxf(v.z, 0.f); v.w = fmaxf(v.w, 0.f);
            }
            *(float4*)(C + off + jj) = v;
        }
    }
}

// ---------------- attention scores: S = scale * Q K^T (causal tiles only) ---
__global__ __launch_bounds__(256) void attn_scores_k(){
    int kt = blockIdx.x, qt = blockIdx.y;
    if (kt > qt) return;
    int bh = blockIdx.z;
    int b = bh >> 4, h = bh & 15;
    __shared__ float Qs[64][65];
    __shared__ float Ks[64][65];
    int tid = threadIdx.x;
    int r = tid >> 2, cs = (tid & 3) * 16;
    const float* qp = g_q + ((size_t)(b * Tn + qt * 64 + r)) * Dn + h * HSn + cs;
    const float* kp = g_k + ((size_t)(b * Tn + kt * 64 + r)) * Dn + h * HSn + cs;
#pragma unroll
    for (int i = 0; i < 4; i++){
        float4 v = *(const float4*)(qp + i * 4);
        Qs[r][cs + i * 4 + 0] = v.x; Qs[r][cs + i * 4 + 1] = v.y;
        Qs[r][cs + i * 4 + 2] = v.z; Qs[r][cs + i * 4 + 3] = v.w;
        float4 w = *(const float4*)(kp + i * 4);
        Ks[r][cs + i * 4 + 0] = w.x; Ks[r][cs + i * 4 + 1] = w.y;
        Ks[r][cs + i * 4 + 2] = w.z; Ks[r][cs + i * 4 + 3] = w.w;
    }
    __syncthreads();
    int tx = tid & 15, ty = tid >> 4;
    float acc[4][4];
#pragma unroll
    for (int i = 0; i < 4; i++)
#pragma unroll
        for (int j = 0; j < 4; j++) acc[i][j] = 0.f;
#pragma unroll 8
    for (int c = 0; c < 64; c++){
        float a[4], bb[4];
#pragma unroll
        for (int i = 0; i < 4; i++) a[i] = Qs[ty * 4 + i][c];
#pragma unroll
        for (int j = 0; j < 4; j++) bb[j] = Ks[tx * 4 + j][c];
#pragma unroll
        for (int i = 0; i < 4; i++)
#pragma unroll
            for (int j = 0; j < 4; j++)
                acc[i][j] += a[i] * bb[j];
    }
    float* sp = g_s + (size_t)bh * Tn * Tn;
#pragma unroll
    for (int i = 0; i < 4; i++){
        int qi = qt * 64 + ty * 4 + i;
#pragma unroll
        for (int j = 0; j < 4; j++){
            int kj = kt * 64 + tx * 4 + j;
            float vv = acc[i][j] * 0.125f;   // 1/sqrt(64)
            if (kj > qi) vv = -3.0e38f;
            sp[(size_t)qi * Tn + kj] = vv;
        }
    }
}

// ---------------- causal softmax (in place), zero-fill masked region --------
__global__ __launch_bounds__(128) void softmax_k(){
    __shared__ float sh[32];
    int row = blockIdx.x;           // 0 .. BHn*Tn-1
    int i = row & (Tn - 1);
    float* sr = g_s + (size_t)row * Tn;
    float mx = -3.0e38f;
    for (int j = threadIdx.x; j <= i; j += 128) mx = fmaxf(mx, sr[j]);
    mx = blockMax(mx, sh);
    float sum = 0.f;
    for (int j = threadIdx.x; j <= i; j += 128){
        float e = expf(sr[j] - mx);
        sr[j] = e;
        sum += e;
    }
    sum = blockSum(sum, sh);
    float inv = 1.f / sum;
    for (int j = threadIdx.x; j <= i; j += 128) sr[j] *= inv;
    for (int j = i + 1 + threadIdx.x; j < Tn; j += 128) sr[j] = 0.f;
}

// ---------------- O = S @ V (batched per bh, causal chunk skipping) ---------
__global__ __launch_bounds__(256) void attn_av_k(){
    int qt = blockIdx.x, bh = blockIdx.y;
    int b = bh >> 4, h = bh & 15;
    __shared__ float Ss[64][65];
    __shared__ float Vs[64][65];
    int tid = threadIdx.x;
    int r = tid >> 2, cs = (tid & 3) * 16;
    int tx = tid & 15, ty = tid >> 4;
    float acc[4][4];
#pragma unroll
    for (int i = 0; i < 4; i++)
#pragma unroll
        for (int j = 0; j < 4; j++) acc[i][j] = 0.f;
    const float* sbase = g_s + (size_t)bh * Tn * Tn;
    for (int kc = 0; kc <= qt; kc++){
        const float* sp = sbase + (size_t)(qt * 64 + r) * Tn + kc * 64 + cs;
        const float* vp = g_v + ((size_t)(b * Tn + kc * 64 + r)) * Dn + h * HSn + cs;
#pragma unroll
        for (int i2 = 0; i2 < 4; i2++){
            float4 a4 = *(const float4*)(sp + i2 * 4);
            Ss[r][cs + i2 * 4 + 0] = a4.x; Ss[r][cs + i2 * 4 + 1] = a4.y;
            Ss[r][cs + i2 * 4 + 2] = a4.z; Ss[r][cs + i2 * 4 + 3] = a4.w;
            float4 b4 = *(const float4*)(vp + i2 * 4);
            Vs[r][cs + i2 * 4 + 0] = b4.x; Vs[r][cs + i2 * 4 + 1] = b4.y;
            Vs[r][cs + i2 * 4 + 2] = b4.z; Vs[r][cs + i2 * 4 + 3] = b4.w;
        }
        __syncthreads();
#pragma unroll 8
        for (int c = 0; c < 64; c++){
            float a[4], bb[4];
#pragma unroll
            for (int i = 0; i < 4; i++) a[i] = Ss[ty * 4 + i][c];
#pragma unroll
            for (int j = 0; j < 4; j++) bb[j] = Vs[c][tx * 4 + j];
#pragma unroll
            for (int i = 0; i < 4; i++)
#pragma unroll
                for (int j = 0; j < 4; j++)
                    acc[i][j] += a[i] * bb[j];
        }
        __syncthreads();
    }
#pragma unroll
    for (int i = 0; i < 4; i++){
        size_t off = ((size_t)(b * Tn + qt * 64 + ty * 4 + i)) * Dn + h * HSn + tx * 4;
#pragma unroll
        for (int j = 0; j < 4; j++)
            g_o[off + j] = acc[i][j];
    }
}

// ---------------- host orchestration ----------------
extern "C" void kernel_launch(void* const* d_in, const int* in_sizes, int n_in,
                              void* d_out, int out_size){
    (void)in_sizes; (void)n_in; (void)out_size;
    const int*   x     = (const int*)  d_in[0];
    const float* ce    = (const float*)d_in[1];
    const float* pe    = (const float*)d_in[2];
    // d_in[3] router_w, d_in[4] router_b: dead code in the reference
    const float* ln1_s = (const float*)d_in[5];
    const float* ln1_b = (const float*)d_in[6];
    const float* wq    = (const float*)d_in[7];
    const float* wk    = (const float*)d_in[8];
    const float* wv    = (const float*)d_in[9];
    const float* wo    = (const float*)d_in[10];
    const float* bo    = (const float*)d_in[11];
    const float* ln2_s = (const float*)d_in[12];
    const float* ln2_b = (const float*)d_in[13];
    const float* w1    = (const float*)d_in[14];
    const float* b1    = (const float*)d_in[15];
    const float* w2    = (const float*)d_in[16];
    const float* b2    = (const float*)d_in[17];
    const float* lnf_s = (const float*)d_in[18];
    const float* lnf_b = (const float*)d_in[19];
    const float* wf    = (const float*)d_in[20];
    const float* bf    = (const float*)d_in[21];

    float *h, *y, *q, *k, *v, *o, *a;
    cudaGetSymbolAddress((void**)&h, g_h);
    cudaGetSymbolAddress((void**)&y, g_y);
    cudaGetSymbolAddress((void**)&q, g_q);
    cudaGetSymbolAddress((void**)&k, g_k);
    cudaGetSymbolAddress((void**)&v, g_v);
    cudaGetSymbolAddress((void**)&o, g_o);
    cudaGetSymbolAddress((void**)&a, g_a);

    embed_k<<<(Mn * Dn) / 256, 256>>>(x, ce, pe);

    dim3 gD(Dn / 128, Mn / 128);    // [2048,1024] GEMMs
    dim3 gF(FFn / 128, Mn / 128);   // [2048,4096]
    dim3 gV(Vn / 128, Mn / 128);    // [2048,32000]

    for (int l = 0; l < Ln; l++){
        ln_k<<<Mn, 256>>>(h, y, ln1_s + l * Dn, ln1_b + l * Dn);
        sgemm_k<<<gD, 256>>>(y, wq + (size_t)l * Dn * Dn, nullptr, nullptr, q, Mn, Dn, Dn, 0);
        sgemm_k<<<gD, 256>>>(y, wk + (size_t)l * Dn * Dn, nullptr, nullptr, k, Mn, Dn, Dn, 0);
        sgemm_k<<<gD, 256>>>(y, wv + (size_t)l * Dn * Dn, nullptr, nullptr, v, Mn, Dn, Dn, 0);
        attn_scores_k<<<dim3(8, 8, BHn), 256>>>();
        softmax_k<<<BHn * Tn, 128>>>();
        attn_av_k<<<dim3(8, BHn), 256>>>();
        sgemm_k<<<gD, 256>>>(o, wo + (size_t)l * Dn * Dn, bo + l * Dn, h, h, Mn, Dn, Dn, 0);
        ln_k<<<Mn, 256>>>(h, y, ln2_s + l * Dn, ln2_b + l * Dn);
        sgemm_k<<<gF, 256>>>(y, w1 + (size_t)l * Dn * FFn, b1 + l * FFn, nullptr, a, Mn, FFn, Dn, 1);
        sgemm_k<<<gD, 256>>>(a, w2 + (size_t)l * FFn * Dn, b2 + l * Dn, h, h, Mn, Dn, FFn, 0);
    }

    ln_k<<<Mn, 256>>>(h, y, lnf_s, lnf_b);
    sgemm_k<<<gV, 256>>>(y, wf, bf, nullptr, (float*)d_out, Mn, Vn, Dn, 0);
}

// round 3
// speedup vs baseline: 2.8224x; 2.8224x over previous
#include <cuda_runtime.h>
#include <cuda_bf16.h>
#include <cstdint>

#define Bn 4
#define Tn 512
#define Dn 1024
#define Hn 16
#define HSn 64
#define Ln 8
#define Vn 32000
#define Mn (Bn*Tn)       // 2048
#define FFn (4*Dn)       // 4096
#define BHn (Bn*Hn)      // 64

typedef __nv_bfloat16 bf16;

// ---------------- fp32 scratch ----------------
__device__ float g_h[Mn*Dn];
__device__ float g_y[Mn*Dn];
__device__ float g_q[Mn*Dn];
__device__ float g_k[Mn*Dn];
__device__ float g_v[Mn*Dn];
__device__ float g_o[Mn*Dn];
__device__ float g_a[Mn*FFn];
__device__ float g_s[(size_t)BHn*Tn*Tn];

// ---------------- bf16 hi/lo planes (activations) ----------------
__device__ bf16 g_yH[Mn*Dn],  g_yL[Mn*Dn];
__device__ bf16 g_qH[Mn*Dn],  g_qL[Mn*Dn];
__device__ bf16 g_kH[Mn*Dn],  g_kL[Mn*Dn];
__device__ bf16 g_vtH[Mn*Dn], g_vtL[Mn*Dn];
__device__ bf16 g_oH[Mn*Dn],  g_oL[Mn*Dn];
__device__ bf16 g_aH[Mn*FFn], g_aL[Mn*FFn];
__device__ bf16 g_sH[(size_t)BHn*Tn*Tn], g_sL[(size_t)BHn*Tn*Tn];

// ---------------- bf16 hi/lo planes (weights, transposed [N,K]) -----------
__device__ bf16 g_wqH[Ln*Dn*Dn], g_wqL[Ln*Dn*Dn];
__device__ bf16 g_wkH[Ln*Dn*Dn], g_wkL[Ln*Dn*Dn];
__device__ bf16 g_wvH[Ln*Dn*Dn], g_wvL[Ln*Dn*Dn];
__device__ bf16 g_woH[Ln*Dn*Dn], g_woL[Ln*Dn*Dn];
__device__ bf16 g_w1H[Ln*Dn*FFn], g_w1L[Ln*Dn*FFn];
__device__ bf16 g_w2H[Ln*Dn*FFn], g_w2L[Ln*Dn*FFn];
__device__ bf16 g_wfH[(size_t)Dn*Vn], g_wfL[(size_t)Dn*Vn];

// ==================== helpers ====================
__device__ __forceinline__ uint32_t smem_u32(const void* p){
    uint32_t a;
    asm("{ .reg .u64 t; cvta.to.shared.u64 t, %1; cvt.u32.u64 %0, t; }" : "=r"(a) : "l"(p));
    return a;
}
#define CP16(dst, src) \
    asm volatile("cp.async.cg.shared.global [%0], [%1], 16;" :: "r"(dst), "l"(src))
#define CP_COMMIT() asm volatile("cp.async.commit_group;" ::: "memory")
#define CP_WAIT1() asm volatile("cp.async.wait_group 1;" ::: "memory")
#define CP_WAIT0() asm volatile("cp.async.wait_group 0;" ::: "memory")

#define LDSM4(r0,r1,r2,r3,addr) \
    asm volatile("ldmatrix.sync.aligned.m8n8.x4.shared.b16 {%0,%1,%2,%3}, [%4];" \
        : "=r"(r0),"=r"(r1),"=r"(r2),"=r"(r3) : "r"(addr))

#define MMA16816(d, a, b) \
    asm volatile("mma.sync.aligned.m16n8k16.row.col.f32.bf16.bf16.f32 " \
        "{%0,%1,%2,%3}, {%4,%5,%6,%7}, {%8,%9}, {%0,%1,%2,%3};" \
        : "+f"((d)[0]),"+f"((d)[1]),"+f"((d)[2]),"+f"((d)[3]) \
        : "r"((a)[0]),"r"((a)[1]),"r"((a)[2]),"r"((a)[3]), "r"((b)[0]),"r"((b)[1]))

// ==================== reductions ====================
__device__ __forceinline__ float warpSum(float v){
#pragma unroll
    for (int o = 16; o > 0; o >>= 1) v += __shfl_down_sync(0xffffffffu, v, o);
    return v;
}
__device__ __forceinline__ float warpMax(float v){
#pragma unroll
    for (int o = 16; o > 0; o >>= 1) v = fmaxf(v, __shfl_down_sync(0xffffffffu, v, o));
    return v;
}
__device__ __forceinline__ float blockSum(float v, float* sh){
    int lane = threadIdx.x & 31, w = threadIdx.x >> 5;
    v = warpSum(v);
    __syncthreads();
    if (lane == 0) sh[w] = v;
    __syncthreads();
    int nw = blockDim.x >> 5;
    v = (threadIdx.x < (unsigned)nw) ? sh[threadIdx.x] : 0.f;
    if (w == 0) v = warpSum(v);
    if (threadIdx.x == 0) sh[0] = v;
    __syncthreads();
    return sh[0];
}
__device__ __forceinline__ float blockMax(float v, float* sh){
    int lane = threadIdx.x & 31, w = threadIdx.x >> 5;
    v = warpMax(v);
    __syncthreads();
    if (lane == 0) sh[w] = v;
    __syncthreads();
    int nw = blockDim.x >> 5;
    v = (threadIdx.x < (unsigned)nw) ? sh[threadIdx.x] : -3.0e38f;
    if (w == 0) v = warpMax(v);
    if (threadIdx.x == 0) sh[0] = v;
    __syncthreads();
    return sh[0];
}

// ==================== small kernels ====================
__global__ void embed_k(const int* __restrict__ x, const float* __restrict__ ce,
                        const float* __restrict__ pe){
    int idx = blockIdx.x * blockDim.x + threadIdx.x;
    int d  = idx & (Dn - 1);
    int mt = idx >> 10;
    int t  = mt & (Tn - 1);
    g_h[idx] = ce[(size_t)x[mt] * Dn + d] + pe[t * Dn + d];
}

__global__ __launch_bounds__(256) void ln_k(const float* __restrict__ in,
                                            float* __restrict__ out,
                                            const float* __restrict__ gs,
                                            const float* __restrict__ gb){
    __shared__ float sh[32];
    int row = blockIdx.x;
    const float* xr = in + (size_t)row * Dn;
    float s = 0.f, sq = 0.f;
    for (int i = threadIdx.x; i < Dn; i += 256){ float v = xr[i]; s += v; sq += v * v; }
    s  = blockSum(s, sh);
    sq = blockSum(sq, sh);
    float mean = s * (1.f / Dn);
    float var  = sq * (1.f / Dn) - mean * mean;
    float r = rsqrtf(var + 1e-5f);
    float* orow = out + (size_t)row * Dn;
    for (int i = threadIdx.x; i < Dn; i += 256)
        orow[i] = (xr[i] - mean) * r * gs[i] + gb[i];
}

__global__ __launch_bounds__(128) void softmax_k(){
    __shared__ float sh[32];
    int row = blockIdx.x;           // 0 .. BHn*Tn-1
    int i = row & (Tn - 1);
    float* sr = g_s + (size_t)row * Tn;
    float mx = -3.0e38f;
    for (int j = threadIdx.x; j <= i; j += 128) mx = fmaxf(mx, sr[j]);
    mx = blockMax(mx, sh);
    float sum = 0.f;
    for (int j = threadIdx.x; j <= i; j += 128){
        float e = expf(sr[j] - mx);
        sr[j] = e;
        sum += e;
    }
    sum = blockSum(sum, sh);
    float inv = 1.f / sum;
    for (int j = threadIdx.x; j <= i; j += 128) sr[j] *= inv;
    for (int j = i + 1 + threadIdx.x; j < Tn; j += 128) sr[j] = 0.f;
}

// elementwise fp32 -> bf16 hi/lo planes (float4 granularity)
__global__ void convA(const float* __restrict__ in, bf16* __restrict__ oh,
                      bf16* __restrict__ ol, int n4){
    int i = blockIdx.x * blockDim.x + threadIdx.x;
    if (i >= n4) return;
    float4 v = ((const float4*)in)[i];
    bf16 h0 = __float2bfloat16(v.x), h1 = __float2bfloat16(v.y);
    bf16 h2 = __float2bfloat16(v.z), h3 = __float2bfloat16(v.w);
    bf16 l0 = __float2bfloat16(v.x - __bfloat162float(h0));
    bf16 l1 = __float2bfloat16(v.y - __bfloat162float(h1));
    bf16 l2 = __float2bfloat16(v.z - __bfloat162float(h2));
    bf16 l3 = __float2bfloat16(v.w - __bfloat162float(h3));
    __nv_bfloat162* ohp = (__nv_bfloat162*)oh;
    __nv_bfloat162* olp = (__nv_bfloat162*)ol;
    ohp[2*i]   = __nv_bfloat162(h0, h1);
    ohp[2*i+1] = __nv_bfloat162(h2, h3);
    olp[2*i]   = __nv_bfloat162(l0, l1);
    olp[2*i+1] = __nv_bfloat162(l2, l3);
}

// transpose + convert: in [R,C] fp32 -> out [C,R] bf16 hi/lo
__global__ __launch_bounds__(256) void convT(const float* __restrict__ in,
                                             bf16* __restrict__ oh, bf16* __restrict__ ol,
                                             int ldin, int ldout, int zH,
                                             long long sIb, long long sIh,
                                             long long sOb, long long sOh){
    __shared__ float t[32][33];
    int z = blockIdx.z, bz = z / zH, hz = z % zH;
    const float* pin = in + bz * sIb + hz * sIh;
    bf16* poh = oh + bz * sOb + hz * sOh;
    bf16* pol = ol + bz * sOb + hz * sOh;
    int cb = blockIdx.x * 32, rb = blockIdx.y * 32;
    int tx = threadIdx.x, ty = threadIdx.y;  // (32, 8)
#pragma unroll
    for (int i = 0; i < 4; i++)
        t[ty + 8*i][tx] = pin[(size_t)(rb + ty + 8*i) * ldin + cb + tx];
    __syncthreads();
#pragma unroll
    for (int i = 0; i < 4; i++){
        float v = t[tx][ty + 8*i];
        bf16 h = __float2bfloat16(v);
        bf16 l = __float2bfloat16(v - __bfloat162float(h));
        size_t o = (size_t)(cb + ty + 8*i) * ldout + rb + tx;
        poh[o] = h; pol[o] = l;
    }
}

// ==================== bf16-split mma.sync GEMM ====================
// C[z][M,N] = A[z][M,K] @ B[z][N,K]^T  via 3-pass split bf16, fp32 accum.
#define F_BIAS   1
#define F_RES    2
#define F_RELU   4
#define F_SCALE  8
#define F_CAUSAL 16

template<int BN>
__global__ __launch_bounds__(256) void gemm_mma(
    const bf16* __restrict__ Ah, const bf16* __restrict__ Al,
    const bf16* __restrict__ Bh, const bf16* __restrict__ Bl,
    const float* __restrict__ bias, const float* __restrict__ res,
    float* __restrict__ C,
    int K, int lda, int ldb, int ldc,
    int zH, long long sAb, long long sAh, long long sBb, long long sBh,
    long long sCb, long long sCh,
    int flags, float scale)
{
    constexpr int BM = 128, BK = 32;
    constexpr int SA = 40;                 // padded smem row (bf16 elems) -> 80B
    constexpr int ABYTES = BM * SA * 2;    // 10240
    constexpr int BBYTES = BN * SA * 2;
    constexpr int STAGE = 2 * ABYTES + 2 * BBYTES;
    constexpr int WN = BN / 2;
    constexpr int NA = WN / 8;             // n atoms per warp

    const int bm = blockIdx.y * BM, bn = blockIdx.x * BN;
    if ((flags & F_CAUSAL) && bn >= bm + BM) return;

    extern __shared__ char sm[];
    const uint32_t smb = smem_u32(sm);

    const int tid = threadIdx.x, lane = tid & 31, wid = tid >> 5;
    const int wm = wid & 3, wn = wid >> 2;

    const int z = blockIdx.z;
    const int bz = z / zH, hz = z % zH;
    const bf16* pAh = Ah + bz * sAb + hz * sAh;
    const bf16* pAl = Al + bz * sAb + hz * sAh;
    const bf16* pBh = Bh + bz * sBb + hz * sBh;
    const bf16* pBl = Bl + bz * sBb + hz * sBh;
    float* pC = C + bz * sCb + hz * sCh;
    const float* pres = res ? (res + bz * sCb + hz * sCh) : nullptr;

    const int nKB = K >> 5;

    auto loadStage = [&](int kb, int s){
        const int k0 = kb * BK;
        const uint32_t stg = smb + s * STAGE;
#pragma unroll
        for (int i = 0; i < 2; i++){             // A: 512 chunks/plane
            int idx = i * 256 + tid;
            int r = idx >> 2, c = idx & 3;
            uint32_t dst = stg + r * 80 + c * 16;
            const bf16* sH = pAh + (size_t)(bm + r) * lda + k0 + c * 8;
            const bf16* sL = pAl + (size_t)(bm + r) * lda + k0 + c * 8;
            CP16(dst, sH);
            CP16(dst + ABYTES, sL);
        }
#pragma unroll
        for (int i = 0; i < BN / 64; i++){       // B: BN*4 chunks/plane
            int idx = i * 256 + tid;
            int r = idx >> 2, c = idx & 3;
            uint32_t dst = stg + 2 * ABYTES + r * 80 + c * 16;
            const bf16* sH = pBh + (size_t)(bn + r) * ldb + k0 + c * 8;
            const bf16* sL = pBl + (size_t)(bn + r) * ldb + k0 + c * 8;
            CP16(dst, sH);
            CP16(dst + BBYTES, sL);
        }
        CP_COMMIT();
    };

    float acc[2][NA][4];
#pragma unroll
    for (int i = 0; i < 2; i++)
#pragma unroll
        for (int j = 0; j < NA; j++)
#pragma unroll
            for (int q = 0; q < 4; q++) acc[i][j][q] = 0.f;

    loadStage(0, 0);

    for (int kb = 0; kb < nKB; kb++){
        const int s = kb & 1;
        if (kb + 1 < nKB){ loadStage(kb + 1, s ^ 1); CP_WAIT1(); }
        else             { CP_WAIT0(); }
        __syncthreads();

        const uint32_t stg = smb + s * STAGE;
#pragma unroll
        for (int ks = 0; ks < 2; ks++){
            const int kc = ks * 16;
            uint32_t a_h[2][4], a_l[2][4];
#pragma unroll
            for (int mi = 0; mi < 2; mi++){
                int row = wm * 32 + mi * 16 + (lane & 15);
                int colb = (kc + ((lane >> 4) << 3)) * 2;
                uint32_t ad = stg + row * 80 + colb;
                LDSM4(a_h[mi][0], a_h[mi][1], a_h[mi][2], a_h[mi][3], ad);
                LDSM4(a_l[mi][0], a_l[mi][1], a_l[mi][2], a_l[mi][3], ad + ABYTES);
            }
            uint32_t b_h[NA][2], b_l[NA][2];
#pragma unroll
            for (int p = 0; p < NA / 2; p++){
                int rowb = wn * WN + p * 16 + (lane & 7) + ((lane >> 4) << 3);
                int colb = (kc + (((lane >> 3) & 1) << 3)) * 2;
                uint32_t ad = stg + 2 * ABYTES + rowb * 80 + colb;
                uint32_t r0, r1, r2, r3;
                LDSM4(r0, r1, r2, r3, ad);
                b_h[2*p][0] = r0; b_h[2*p][1] = r1;
                b_h[2*p+1][0] = r2; b_h[2*p+1][1] = r3;
                LDSM4(r0, r1, r2, r3, ad + BBYTES);
                b_l[2*p][0] = r0; b_l[2*p][1] = r1;
                b_l[2*p+1][0] = r2; b_l[2*p+1][1] = r3;
            }
#pragma unroll
            for (int mi = 0; mi < 2; mi++)
#pragma unroll
                for (int ni = 0; ni < NA; ni++){
                    MMA16816(acc[mi][ni], a_h[mi], b_h[ni]);
                    MMA16816(acc[mi][ni], a_l[mi], b_h[ni]);
                    MMA16816(acc[mi][ni], a_h[mi], b_l[ni]);
                }
        }
        __syncthreads();
    }

    // epilogue
#pragma unroll
    for (int mi = 0; mi < 2; mi++){
#pragma unroll
        for (int ni = 0; ni < NA; ni++){
            int r0 = bm + wm * 32 + mi * 16 + (lane >> 2);
            int c0 = bn + wn * WN + ni * 8 + (lane & 3) * 2;
#pragma unroll
            for (int half = 0; half < 2; half++){
                int r = r0 + half * 8;
                float vx = acc[mi][ni][half * 2 + 0];
                float vy = acc[mi][ni][half * 2 + 1];
                if (flags & F_SCALE){ vx *= scale; vy *= scale; }
                if (flags & F_BIAS){ vx += bias[c0]; vy += bias[c0 + 1]; }
                if (flags & F_RES){
                    const float* rp = pres + (size_t)r * ldc + c0;
                    vx += rp[0]; vy += rp[1];
                }
                if (flags & F_RELU){ vx = fmaxf(vx, 0.f); vy = fmaxf(vy, 0.f); }
                if (flags & F_CAUSAL){
                    if (c0 > r)     vx = -3.0e38f;
                    if (c0 + 1 > r) vy = -3.0e38f;
                }
                float2 o2; o2.x = vx; o2.y = vy;
                *(float2*)(pC + (size_t)r * ldc + c0) = o2;
            }
        }
    }
}

// ==================== host orchestration ====================
extern "C" void kernel_launch(void* const* d_in, const int* in_sizes, int n_in,
                              void* d_out, int out_size){
    (void)in_sizes; (void)n_in; (void)out_size;
    const int*   x     = (const int*)  d_in[0];
    const float* ce    = (const float*)d_in[1];
    const float* pe    = (const float*)d_in[2];
    const float* ln1_s = (const float*)d_in[5];
    const float* ln1_b = (const float*)d_in[6];
    const float* wq    = (const float*)d_in[7];
    const float* wk    = (const float*)d_in[8];
    const float* wv    = (const float*)d_in[9];
    const float* wo    = (const float*)d_in[10];
    const float* bo    = (const float*)d_in[11];
    const float* ln2_s = (const float*)d_in[12];
    const float* ln2_b = (const float*)d_in[13];
    const float* w1    = (const float*)d_in[14];
    const float* b1    = (const float*)d_in[15];
    const float* w2    = (const float*)d_in[16];
    const float* b2    = (const float*)d_in[17];
    const float* lnf_s = (const float*)d_in[18];
    const float* lnf_b = (const float*)d_in[19];
    const float* wf    = (const float*)d_in[20];
    const float* bf    = (const float*)d_in[21];

    float *h, *y, *q, *k, *v, *o, *a, *s;
    cudaGetSymbolAddress((void**)&h, g_h);
    cudaGetSymbolAddress((void**)&y, g_y);
    cudaGetSymbolAddress((void**)&q, g_q);
    cudaGetSymbolAddress((void**)&k, g_k);
    cudaGetSymbolAddress((void**)&v, g_v);
    cudaGetSymbolAddress((void**)&o, g_o);
    cudaGetSymbolAddress((void**)&a, g_a);
    cudaGetSymbolAddress((void**)&s, g_s);

    bf16 *yH,*yL,*qH,*qL,*kH,*kL,*vtH,*vtL,*oH,*oL,*aH,*aL,*sH,*sL;
    cudaGetSymbolAddress((void**)&yH, g_yH);  cudaGetSymbolAddress((void**)&yL, g_yL);
    cudaGetSymbolAddress((void**)&qH, g_qH);  cudaGetSymbolAddress((void**)&qL, g_qL);
    cudaGetSymbolAddress((void**)&kH, g_kH);  cudaGetSymbolAddress((void**)&kL, g_kL);
    cudaGetSymbolAddress((void**)&vtH, g_vtH);cudaGetSymbolAddress((void**)&vtL, g_vtL);
    cudaGetSymbolAddress((void**)&oH, g_oH);  cudaGetSymbolAddress((void**)&oL, g_oL);
    cudaGetSymbolAddress((void**)&aH, g_aH);  cudaGetSymbolAddress((void**)&aL, g_aL);
    cudaGetSymbolAddress((void**)&sH, g_sH);  cudaGetSymbolAddress((void**)&sL, g_sL);

    bf16 *wqH,*wqL,*wkH,*wkL,*wvH,*wvL,*woH,*woL,*w1H,*w1L,*w2H,*w2L,*wfH,*wfL;
    cudaGetSymbolAddress((void**)&wqH, g_wqH); cudaGetSymbolAddress((void**)&wqL, g_wqL);
    cudaGetSymbolAddress((void**)&wkH, g_wkH); cudaGetSymbolAddress((void**)&wkL, g_wkL);
    cudaGetSymbolAddress((void**)&wvH, g_wvH); cudaGetSymbolAddress((void**)&wvL, g_wvL);
    cudaGetSymbolAddress((void**)&woH, g_woH); cudaGetSymbolAddress((void**)&woL, g_woL);
    cudaGetSymbolAddress((void**)&w1H, g_w1H); cudaGetSymbolAddress((void**)&w1L, g_w1L);
    cudaGetSymbolAddress((void**)&w2H, g_w2H); cudaGetSymbolAddress((void**)&w2L, g_w2L);
    cudaGetSymbolAddress((void**)&wfH, g_wfH); cudaGetSymbolAddress((void**)&wfL, g_wfL);

    // dynamic smem: BN=128 -> 2*(2*10240+2*10240)=81920 ; BN=64 -> 61440
    const int SM128 = 81920, SM64 = 61440;
    cudaFuncSetAttribute(gemm_mma<128>, cudaFuncAttributeMaxDynamicSharedMemorySize, SM128);
    cudaFuncSetAttribute(gemm_mma<64>,  cudaFuncAttributeMaxDynamicSharedMemorySize, SM64);

    dim3 cb(32, 8);
    const long long DD = (long long)Dn * Dn;
    const long long DF = (long long)Dn * FFn;
    convT<<<dim3(Dn/32, Dn/32, Ln), cb>>>(wq, wqH, wqL, Dn, Dn, 1, DD, 0, DD, 0);
    convT<<<dim3(Dn/32, Dn/32, Ln), cb>>>(wk, wkH, wkL, Dn, Dn, 1, DD, 0, DD, 0);
    convT<<<dim3(Dn/32, Dn/32, Ln), cb>>>(wv, wvH, wvL, Dn, Dn, 1, DD, 0, DD, 0);
    convT<<<dim3(Dn/32, Dn/32, Ln), cb>>>(wo, woH, woL, Dn, Dn, 1, DD, 0, DD, 0);
    convT<<<dim3(FFn/32, Dn/32, Ln), cb>>>(w1, w1H, w1L, FFn, Dn, 1, DF, 0, DF, 0);
    convT<<<dim3(Dn/32, FFn/32, Ln), cb>>>(w2, w2H, w2L, Dn, FFn, 1, DF, 0, DF, 0);
    convT<<<dim3(Vn/32, Dn/32, 1),  cb>>>(wf, wfH, wfL, Vn, Dn, 1, 0, 0, 0, 0);

    embed_k<<<(Mn * Dn) / 256, 256>>>(x, ce, pe);

    const int nD4 = Mn * Dn / 4;
    const int nF4 = Mn * FFn / 4;
    const int nS4 = BHn * Tn * Tn / 4;
    const long long SAB = (long long)Tn * Dn;
    const long long SS1 = (long long)Tn * Tn;
    const long long SVT = (long long)HSn * Tn;

    for (int l = 0; l < Ln; l++){
        ln_k<<<Mn, 256>>>(h, y, ln1_s + l*Dn, ln1_b + l*Dn);
        convA<<<(nD4 + 255)/256, 256>>>(y, yH, yL, nD4);

        gemm_mma<128><<<dim3(8,16,1), 256, SM128>>>(yH, yL, wqH + (size_t)l*DD, wqL + (size_t)l*DD,
            nullptr, nullptr, q, Dn, Dn, Dn, Dn, 1, 0,0,0,0,0,0, 0, 1.f);
        gemm_mma<128><<<dim3(8,16,1), 256, SM128>>>(yH, yL, wkH + (size_t)l*DD, wkL + (size_t)l*DD,
            nullptr, nullptr, k, Dn, Dn, Dn, Dn, 1, 0,0,0,0,0,0, 0, 1.f);
        gemm_mma<128><<<dim3(8,16,1), 256, SM128>>>(yH, yL, wvH + (size_t)l*DD, wvL + (size_t)l*DD,
            nullptr, nullptr, v, Dn, Dn, Dn, Dn, 1, 0,0,0,0,0,0, 0, 1.f);

        convA<<<(nD4 + 255)/256, 256>>>(q, qH, qL, nD4);
        convA<<<(nD4 + 255)/256, 256>>>(k, kH, kL, nD4);
        convT<<<dim3(HSn/32, Tn/32, BHn), cb>>>(v, vtH, vtL, Dn, Tn, Hn,
            SAB, (long long)HSn, (long long)Hn*SVT, SVT);

        gemm_mma<128><<<dim3(4,4,BHn), 256, SM128>>>(qH, qL, kH, kL, nullptr, nullptr, s,
            HSn, Dn, Dn, Tn, Hn, SAB, (long long)HSn, SAB, (long long)HSn,
            (long long)Hn*SS1, SS1, F_SCALE | F_CAUSAL, 0.125f);
        softmax_k<<<BHn*Tn, 128>>>();
        convA<<<(nS4 + 255)/256, 256>>>(s, sH, sL, nS4);

        gemm_mma<64><<<dim3(1,4,BHn), 256, SM64>>>(sH, sL, vtH, vtL, nullptr, nullptr, o,
            Tn, Tn, Tn, Dn, Hn, (long long)Hn*SS1, SS1, (long long)Hn*SVT, SVT,
            SAB, (long long)HSn, 0, 1.f);

        convA<<<(nD4 + 255)/256, 256>>>(o, oH, oL, nD4);
        gemm_mma<128><<<dim3(8,16,1), 256, SM128>>>(oH, oL, woH + (size_t)l*DD, woL + (size_t)l*DD,
            bo + l*Dn, h, h, Dn, Dn, Dn, Dn, 1, 0,0,0,0,0,0, F_BIAS | F_RES, 1.f);

        ln_k<<<Mn, 256>>>(h, y, ln2_s + l*Dn, ln2_b + l*Dn);
        convA<<<(nD4 + 255)/256, 256>>>(y, yH, yL, nD4);
        gemm_mma<128><<<dim3(32,16,1), 256, SM128>>>(yH, yL, w1H + (size_t)l*DF, w1L + (size_t)l*DF,
            b1 + l*FFn, nullptr, a, Dn, Dn, Dn, FFn, 1, 0,0,0,0,0,0, F_BIAS | F_RELU, 1.f);
        convA<<<(nF4 + 255)/256, 256>>>(a, aH, aL, nF4);
        gemm_mma<128><<<dim3(8,16,1), 256, SM128>>>(aH, aL, w2H + (size_t)l*DF, w2L + (size_t)l*DF,
            b2 + l*Dn, h, h, FFn, FFn, FFn, Dn, 1, 0,0,0,0,0,0, F_BIAS | F_RES, 1.f);
    }

    ln_k<<<Mn, 256>>>(h, y, lnf_s, lnf_b);
    convA<<<(nD4 + 255)/256, 256>>>(y, yH, yL, nD4);
    gemm_mma<128><<<dim3(Vn/128, 16, 1), 256, SM128>>>(yH, yL, wfH, wfL,
        bf, nullptr, (float*)d_out, Dn, Dn, Dn, Vn, 1, 0,0,0,0,0,0, F_BIAS, 1.f);
}

// round 4
// speedup vs baseline: 2.8460x; 1.0084x over previous
#include <cuda_runtime.h>
#include <cuda_bf16.h>
#include <cstdint>

#define Bn 4
#define Tn 512
#define Dn 1024
#define Hn 16
#define HSn 64
#define Ln 8
#define Vn 32000
#define Mn (Bn*Tn)       // 2048
#define FFn (4*Dn)       // 4096
#define BHn (Bn*Hn)      // 64

typedef __nv_bfloat16 bf16;

// ---------------- fp32 scratch ----------------
__device__ float g_h[Mn*Dn];
__device__ float g_y[Mn*Dn];
__device__ float g_q[Mn*Dn];
__device__ float g_k[Mn*Dn];
__device__ float g_v[Mn*Dn];
__device__ float g_o[Mn*Dn];
__device__ float g_a[Mn*FFn];
__device__ float g_s[(size_t)BHn*Tn*Tn];

// ---------------- bf16 hi/lo planes (activations) ----------------
__device__ bf16 g_yH[Mn*Dn],  g_yL[Mn*Dn];
__device__ bf16 g_qH[Mn*Dn],  g_qL[Mn*Dn];
__device__ bf16 g_kH[Mn*Dn],  g_kL[Mn*Dn];
__device__ bf16 g_vtH[Mn*Dn], g_vtL[Mn*Dn];
__device__ bf16 g_oH[Mn*Dn],  g_oL[Mn*Dn];
__device__ bf16 g_aH[Mn*FFn], g_aL[Mn*FFn];
__device__ bf16 g_sH[(size_t)BHn*Tn*Tn], g_sL[(size_t)BHn*Tn*Tn];

// ---------------- bf16 hi/lo planes (weights, transposed [N,K]) -----------
__device__ bf16 g_wqH[Ln*Dn*Dn], g_wqL[Ln*Dn*Dn];
__device__ bf16 g_wkH[Ln*Dn*Dn], g_wkL[Ln*Dn*Dn];
__device__ bf16 g_wvH[Ln*Dn*Dn], g_wvL[Ln*Dn*Dn];
__device__ bf16 g_woH[Ln*Dn*Dn], g_woL[Ln*Dn*Dn];
__device__ bf16 g_w1H[Ln*Dn*FFn], g_w1L[Ln*Dn*FFn];
__device__ bf16 g_w2H[Ln*Dn*FFn], g_w2L[Ln*Dn*FFn];
__device__ bf16 g_wfH[(size_t)Dn*Vn], g_wfL[(size_t)Dn*Vn];

// ==================== helpers ====================
__device__ __forceinline__ uint32_t smem_u32(const void* p){
    uint32_t a;
    asm("{ .reg .u64 t; cvta.to.shared.u64 t, %1; cvt.u32.u64 %0, t; }" : "=r"(a) : "l"(p));
    return a;
}
#define CP16(dst, src) \
    asm volatile("cp.async.cg.shared.global [%0], [%1], 16;" :: "r"(dst), "l"(src))
#define CP_COMMIT() asm volatile("cp.async.commit_group;" ::: "memory")
#define CP_WAIT1() asm volatile("cp.async.wait_group 1;" ::: "memory")
#define CP_WAIT0() asm volatile("cp.async.wait_group 0;" ::: "memory")

#define LDSM4(r0,r1,r2,r3,addr) \
    asm volatile("ldmatrix.sync.aligned.m8n8.x4.shared.b16 {%0,%1,%2,%3}, [%4];" \
        : "=r"(r0),"=r"(r1),"=r"(r2),"=r"(r3) : "r"(addr))

#define MMA16816(d, a, b) \
    asm volatile("mma.sync.aligned.m16n8k16.row.col.f32.bf16.bf16.f32 " \
        "{%0,%1,%2,%3}, {%4,%5,%6,%7}, {%8,%9}, {%0,%1,%2,%3};" \
        : "+f"((d)[0]),"+f"((d)[1]),"+f"((d)[2]),"+f"((d)[3]) \
        : "r"((a)[0]),"r"((a)[1]),"r"((a)[2]),"r"((a)[3]), "r"((b)[0]),"r"((b)[1]))

// ==================== reductions ====================
__device__ __forceinline__ float warpSum(float v){
#pragma unroll
    for (int o = 16; o > 0; o >>= 1) v += __shfl_down_sync(0xffffffffu, v, o);
    return v;
}
__device__ __forceinline__ float warpMax(float v){
#pragma unroll
    for (int o = 16; o > 0; o >>= 1) v = fmaxf(v, __shfl_down_sync(0xffffffffu, v, o));
    return v;
}
__device__ __forceinline__ float blockSum(float v, float* sh){
    int lane = threadIdx.x & 31, w = threadIdx.x >> 5;
    v = warpSum(v);
    __syncthreads();
    if (lane == 0) sh[w] = v;
    __syncthreads();
    int nw = blockDim.x >> 5;
    v = (threadIdx.x < (unsigned)nw) ? sh[threadIdx.x] : 0.f;
    if (w == 0) v = warpSum(v);
    if (threadIdx.x == 0) sh[0] = v;
    __syncthreads();
    return sh[0];
}
__device__ __forceinline__ float blockMax(float v, float* sh){
    int lane = threadIdx.x & 31, w = threadIdx.x >> 5;
    v = warpMax(v);
    __syncthreads();
    if (lane == 0) sh[w] = v;
    __syncthreads();
    int nw = blockDim.x >> 5;
    v = (threadIdx.x < (unsigned)nw) ? sh[threadIdx.x] : -3.0e38f;
    if (w == 0) v = warpMax(v);
    if (threadIdx.x == 0) sh[0] = v;
    __syncthreads();
    return sh[0];
}

// ==================== small kernels ====================
__global__ void embed_k(const int* __restrict__ x, const float* __restrict__ ce,
                        const float* __restrict__ pe){
    int idx = blockIdx.x * blockDim.x + threadIdx.x;
    int d  = idx & (Dn - 1);
    int mt = idx >> 10;
    int t  = mt & (Tn - 1);
    g_h[idx] = ce[(size_t)x[mt] * Dn + d] + pe[t * Dn + d];
}

__global__ __launch_bounds__(256) void ln_k(const float* __restrict__ in,
                                            float* __restrict__ out,
                                            const float* __restrict__ gs,
                                            const float* __restrict__ gb){
    __shared__ float sh[32];
    int row = blockIdx.x;
    const float* xr = in + (size_t)row * Dn;
    float s = 0.f, sq = 0.f;
    for (int i = threadIdx.x; i < Dn; i += 256){ float v = xr[i]; s += v; sq += v * v; }
    s  = blockSum(s, sh);
    sq = blockSum(sq, sh);
    float mean = s * (1.f / Dn);
    float var  = sq * (1.f / Dn) - mean * mean;
    float r = rsqrtf(var + 1e-5f);
    float* orow = out + (size_t)row * Dn;
    for (int i = threadIdx.x; i < Dn; i += 256)
        orow[i] = (xr[i] - mean) * r * gs[i] + gb[i];
}

__global__ __launch_bounds__(128) void softmax_k(){
    __shared__ float sh[32];
    int row = blockIdx.x;           // 0 .. BHn*Tn-1
    int i = row & (Tn - 1);
    float* sr = g_s + (size_t)row * Tn;
    float mx = -3.0e38f;
    for (int j = threadIdx.x; j <= i; j += 128) mx = fmaxf(mx, sr[j]);
    mx = blockMax(mx, sh);
    float sum = 0.f;
    for (int j = threadIdx.x; j <= i; j += 128){
        float e = expf(sr[j] - mx);
        sr[j] = e;
        sum += e;
    }
    sum = blockSum(sum, sh);
    float inv = 1.f / sum;
    for (int j = threadIdx.x; j <= i; j += 128) sr[j] *= inv;
    for (int j = i + 1 + threadIdx.x; j < Tn; j += 128) sr[j] = 0.f;
}

// elementwise fp32 -> bf16 hi/lo planes (float4 granularity)
__global__ void convA(const float* __restrict__ in, bf16* __restrict__ oh,
                      bf16* __restrict__ ol, int n4){
    int i = blockIdx.x * blockDim.x + threadIdx.x;
    if (i >= n4) return;
    float4 v = ((const float4*)in)[i];
    bf16 h0 = __float2bfloat16(v.x), h1 = __float2bfloat16(v.y);
    bf16 h2 = __float2bfloat16(v.z), h3 = __float2bfloat16(v.w);
    bf16 l0 = __float2bfloat16(v.x - __bfloat162float(h0));
    bf16 l1 = __float2bfloat16(v.y - __bfloat162float(h1));
    bf16 l2 = __float2bfloat16(v.z - __bfloat162float(h2));
    bf16 l3 = __float2bfloat16(v.w - __bfloat162float(h3));
    __nv_bfloat162* ohp = (__nv_bfloat162*)oh;
    __nv_bfloat162* olp = (__nv_bfloat162*)ol;
    ohp[2*i]   = __nv_bfloat162(h0, h1);
    ohp[2*i+1] = __nv_bfloat162(h2, h3);
    olp[2*i]   = __nv_bfloat162(l0, l1);
    olp[2*i+1] = __nv_bfloat162(l2, l3);
}

// transpose + convert: in [R,C] fp32 -> out [C,R] bf16 hi/lo
__global__ __launch_bounds__(256) void convT(const float* __restrict__ in,
                                             bf16* __restrict__ oh, bf16* __restrict__ ol,
                                             int ldin, int ldout, int zH,
                                             long long sIb, long long sIh,
                                             long long sOb, long long sOh){
    __shared__ float t[32][33];
    int z = blockIdx.z, bz = z / zH, hz = z % zH;
    const float* pin = in + bz * sIb + hz * sIh;
    bf16* poh = oh + bz * sOb + hz * sOh;
    bf16* pol = ol + bz * sOb + hz * sOh;
    int cb = blockIdx.x * 32, rb = blockIdx.y * 32;
    int tx = threadIdx.x, ty = threadIdx.y;  // (32, 8)
#pragma unroll
    for (int i = 0; i < 4; i++)
        t[ty + 8*i][tx] = pin[(size_t)(rb + ty + 8*i) * ldin + cb + tx];
    __syncthreads();
#pragma unroll
    for (int i = 0; i < 4; i++){
        float v = t[tx][ty + 8*i];
        bf16 h = __float2bfloat16(v);
        bf16 l = __float2bfloat16(v - __bfloat162float(h));
        size_t o = (size_t)(cb + ty + 8*i) * ldout + rb + tx;
        poh[o] = h; pol[o] = l;
    }
}

// ==================== bf16-split mma.sync GEMM ====================
// C[z][M,N] = A[z][M,K] @ B[z][N,K]^T  via 3-pass split bf16, fp32 accum.
#define F_BIAS   1
#define F_RES    2
#define F_RELU   4
#define F_SCALE  8
#define F_CAUSAL 16

template<int BN>
__global__ __launch_bounds__(256) void gemm_mma(
    const bf16* __restrict__ Ah, const bf16* __restrict__ Al,
    const bf16* __restrict__ Bh, const bf16* __restrict__ Bl,
    const float* __restrict__ bias, const float* __restrict__ res,
    float* __restrict__ C,
    int K, int lda, int ldb, int ldc,
    int zH, long long sAb, long long sAh, long long sBb, long long sBh,
    long long sCb, long long sCh,
    int flags, float scale)
{
    constexpr int BM = 128, BK = 32;
    constexpr int SA = 40;                 // padded smem row (bf16 elems) -> 80B
    constexpr int ABYTES = BM * SA * 2;    // 10240
    constexpr int BBYTES = BN * SA * 2;
    constexpr int STAGE = 2 * ABYTES + 2 * BBYTES;
    constexpr int WN = BN / 2;
    constexpr int NA = WN / 8;             // n atoms per warp

    const int bm = blockIdx.y * BM, bn = blockIdx.x * BN;
    if ((flags & F_CAUSAL) && bn >= bm + BM) return;

    extern __shared__ char sm[];
    const uint32_t smb = smem_u32(sm);

    const int tid = threadIdx.x, lane = tid & 31, wid = tid >> 5;
    const int wm = wid & 3, wn = wid >> 2;

    const int z = blockIdx.z;
    const int bz = z / zH, hz = z % zH;
    const bf16* pAh = Ah + bz * sAb + hz * sAh;
    const bf16* pAl = Al + bz * sAb + hz * sAh;
    const bf16* pBh = Bh + bz * sBb + hz * sBh;
    const bf16* pBl = Bl + bz * sBb + hz * sBh;
    float* pC = C + bz * sCb + hz * sCh;
    const float* pres = res ? (res + bz * sCb + hz * sCh) : nullptr;

    const int nKB = K >> 5;

    auto loadStage = [&](int kb, int s){
        const int k0 = kb * BK;
        const uint32_t stg = smb + s * STAGE;
#pragma unroll
        for (int i = 0; i < 2; i++){             // A: 512 chunks/plane
            int idx = i * 256 + tid;
            int r = idx >> 2, c = idx & 3;
            uint32_t dst = stg + r * 80 + c * 16;
            const bf16* sH = pAh + (size_t)(bm + r) * lda + k0 + c * 8;
            const bf16* sL = pAl + (size_t)(bm + r) * lda + k0 + c * 8;
            CP16(dst, sH);
            CP16(dst + ABYTES, sL);
        }
#pragma unroll
        for (int i = 0; i < BN / 64; i++){       // B: BN*4 chunks/plane
            int idx = i * 256 + tid;
            int r = idx >> 2, c = idx & 3;
            uint32_t dst = stg + 2 * ABYTES + r * 80 + c * 16;
            const bf16* sH = pBh + (size_t)(bn + r) * ldb + k0 + c * 8;
            const bf16* sL = pBl + (size_t)(bn + r) * ldb + k0 + c * 8;
            CP16(dst, sH);
            CP16(dst + BBYTES, sL);
        }
        CP_COMMIT();
    };

    float acc[2][NA][4];
#pragma unroll
    for (int i = 0; i < 2; i++)
#pragma unroll
        for (int j = 0; j < NA; j++)
#pragma unroll
            for (int q = 0; q < 4; q++) acc[i][j][q] = 0.f;

    loadStage(0, 0);

    for (int kb = 0; kb < nKB; kb++){
        const int s = kb & 1;
        if (kb + 1 < nKB){ loadStage(kb + 1, s ^ 1); CP_WAIT1(); }
        else             { CP_WAIT0(); }
        __syncthreads();

        const uint32_t stg = smb + s * STAGE;
#pragma unroll
        for (int ks = 0; ks < 2; ks++){
            const int kc = ks * 16;
            uint32_t a_h[2][4], a_l[2][4];
#pragma unroll
            for (int mi = 0; mi < 2; mi++){
                int row = wm * 32 + mi * 16 + (lane & 15);
                int colb = (kc + ((lane >> 4) << 3)) * 2;
                uint32_t ad = stg + row * 80 + colb;
                LDSM4(a_h[mi][0], a_h[mi][1], a_h[mi][2], a_h[mi][3], ad);
                LDSM4(a_l[mi][0], a_l[mi][1], a_l[mi][2], a_l[mi][3], ad + ABYTES);
            }
            uint32_t b_h[NA][2], b_l[NA][2];
#pragma unroll
            for (int p = 0; p < NA / 2; p++){
                int rowb = wn * WN + p * 16 + (lane & 7) + ((lane >> 4) << 3);
                int colb = (kc + (((lane >> 3) & 1) << 3)) * 2;
                uint32_t ad = stg + 2 * ABYTES + rowb * 80 + colb;
                uint32_t r0, r1, r2, r3;
                LDSM4(r0, r1, r2, r3, ad);
                b_h[2*p][0] = r0; b_h[2*p][1] = r1;
                b_h[2*p+1][0] = r2; b_h[2*p+1][1] = r3;
                LDSM4(r0, r1, r2, r3, ad + BBYTES);
                b_l[2*p][0] = r0; b_l[2*p][1] = r1;
                b_l[2*p+1][0] = r2; b_l[2*p+1][1] = r3;
            }
#pragma unroll
            for (int mi = 0; mi < 2; mi++)
#pragma unroll
                for (int ni = 0; ni < NA; ni++){
                    MMA16816(acc[mi][ni], a_h[mi], b_h[ni]);
                    MMA16816(acc[mi][ni], a_l[mi], b_h[ni]);
                    MMA16816(acc[mi][ni], a_h[mi], b_l[ni]);
                }
        }
        __syncthreads();
    }

    // epilogue
#pragma unroll
    for (int mi = 0; mi < 2; mi++){
#pragma unroll
        for (int ni = 0; ni < NA; ni++){
            int r0 = bm + wm * 32 + mi * 16 + (lane >> 2);
            int c0 = bn + wn * WN + ni * 8 + (lane & 3) * 2;
#pragma unroll
            for (int half = 0; half < 2; half++){
                int r = r0 + half * 8;
                float vx = acc[mi][ni][half * 2 + 0];
                float vy = acc[mi][ni][half * 2 + 1];
                if (flags & F_SCALE){ vx *= scale; vy *= scale; }
                if (flags & F_BIAS){ vx += bias[c0]; vy += bias[c0 + 1]; }
                if (flags & F_RES){
                    const float* rp = pres + (size_t)r * ldc + c0;
                    vx += rp[0]; vy += rp[1];
                }
                if (flags & F_RELU){ vx = fmaxf(vx, 0.f); vy = fmaxf(vy, 0.f); }
                if (flags & F_CAUSAL){
                    if (c0 > r)     vx = -3.0e38f;
                    if (c0 + 1 > r) vy = -3.0e38f;
                }
                float2 o2; o2.x = vx; o2.y = vy;
                *(float2*)(pC + (size_t)r * ldc + c0) = o2;
            }
        }
    }
}

// ==================== host orchestration ====================
extern "C" void kernel_launch(void* const* d_in, const int* in_sizes, int n_in,
                              void* d_out, int out_size){
    (void)in_sizes; (void)n_in; (void)out_size;
    const int*   x     = (const int*)  d_in[0];
    const float* ce    = (const float*)d_in[1];
    const float* pe    = (const float*)d_in[2];
    const float* ln1_s = (const float*)d_in[5];
    const float* ln1_b = (const float*)d_in[6];
    const float* wq    = (const float*)d_in[7];
    const float* wk    = (const float*)d_in[8];
    const float* wv    = (const float*)d_in[9];
    const float* wo    = (const float*)d_in[10];
    const float* bo    = (const float*)d_in[11];
    const float* ln2_s = (const float*)d_in[12];
    const float* ln2_b = (const float*)d_in[13];
    const float* w1    = (const float*)d_in[14];
    const float* b1    = (const float*)d_in[15];
    const float* w2    = (const float*)d_in[16];
    const float* b2    = (const float*)d_in[17];
    const float* lnf_s = (const float*)d_in[18];
    const float* lnf_b = (const float*)d_in[19];
    const float* wf    = (const float*)d_in[20];
    const float* bf    = (const float*)d_in[21];

    float *h, *y, *q, *k, *v, *o, *a, *s;
    cudaGetSymbolAddress((void**)&h, g_h);
    cudaGetSymbolAddress((void**)&y, g_y);
    cudaGetSymbolAddress((void**)&q, g_q);
    cudaGetSymbolAddress((void**)&k, g_k);
    cudaGetSymbolAddress((void**)&v, g_v);
    cudaGetSymbolAddress((void**)&o, g_o);
    cudaGetSymbolAddress((void**)&a, g_a);
    cudaGetSymbolAddress((void**)&s, g_s);

    bf16 *yH,*yL,*qH,*qL,*kH,*kL,*vtH,*vtL,*oH,*oL,*aH,*aL,*sH,*sL;
    cudaGetSymbolAddress((void**)&yH, g_yH);  cudaGetSymbolAddress((void**)&yL, g_yL);
    cudaGetSymbolAddress((void**)&qH, g_qH);  cudaGetSymbolAddress((void**)&qL, g_qL);
    cudaGetSymbolAddress((void**)&kH, g_kH);  cudaGetSymbolAddress((void**)&kL, g_kL);
    cudaGetSymbolAddress((void**)&vtH, g_vtH);cudaGetSymbolAddress((void**)&vtL, g_vtL);
    cudaGetSymbolAddress((void**)&oH, g_oH);  cudaGetSymbolAddress((void**)&oL, g_oL);
    cudaGetSymbolAddress((void**)&aH, g_aH);  cudaGetSymbolAddress((void**)&aL, g_aL);
    cudaGetSymbolAddress((void**)&sH, g_sH);  cudaGetSymbolAddress((void**)&sL, g_sL);

    bf16 *wqH,*wqL,*wkH,*wkL,*wvH,*wvL,*woH,*woL,*w1H,*w1L,*w2H,*w2L,*wfH,*wfL;
    cudaGetSymbolAddress((void**)&wqH, g_wqH); cudaGetSymbolAddress((void**)&wqL, g_wqL);
    cudaGetSymbolAddress((void**)&wkH, g_wkH); cudaGetSymbolAddress((void**)&wkL, g_wkL);
    cudaGetSymbolAddress((void**)&wvH, g_wvH); cudaGetSymbolAddress((void**)&wvL, g_wvL);
    cudaGetSymbolAddress((void**)&woH, g_woH); cudaGetSymbolAddress((void**)&woL, g_woL);
    cudaGetSymbolAddress((void**)&w1H, g_w1H); cudaGetSymbolAddress((void**)&w1L, g_w1L);
    cudaGetSymbolAddress((void**)&w2H, g_w2H); cudaGetSymbolAddress((void**)&w2L, g_w2L);
    cudaGetSymbolAddress((void**)&wfH, g_wfH); cudaGetSymbolAddress((void**)&wfL, g_wfL);

    // dynamic smem: BN=128 -> 2*(2*10240+2*10240)=81920 ; BN=64 -> 61440
    const int SM128 = 81920, SM64 = 61440;
    cudaFuncSetAttribute(gemm_mma<128>, cudaFuncAttributeMaxDynamicSharedMemorySize, SM128);
    cudaFuncSetAttribute(gemm_mma<64>,  cudaFuncAttributeMaxDynamicSharedMemorySize, SM64);

    dim3 cb(32, 8);
    const long long DD = (long long)Dn * Dn;
    const long long DF = (long long)Dn * FFn;
    convT<<<dim3(Dn/32, Dn/32, Ln), cb>>>(wq, wqH, wqL, Dn, Dn, 1, DD, 0, DD, 0);
    convT<<<dim3(Dn/32, Dn/32, Ln), cb>>>(wk, wkH, wkL, Dn, Dn, 1, DD, 0, DD, 0);
    convT<<<dim3(Dn/32, Dn/32, Ln), cb>>>(wv, wvH, wvL, Dn, Dn, 1, DD, 0, DD, 0);
    convT<<<dim3(Dn/32, Dn/32, Ln), cb>>>(wo, woH, woL, Dn, Dn, 1, DD, 0, DD, 0);
    convT<<<dim3(FFn/32, Dn/32, Ln), cb>>>(w1, w1H, w1L, FFn, Dn, 1, DF, 0, DF, 0);
    convT<<<dim3(Dn/32, FFn/32, Ln), cb>>>(w2, w2H, w2L, Dn, FFn, 1, DF, 0, DF, 0);
    convT<<<dim3(Vn/32, Dn/32, 1),  cb>>>(wf, wfH, wfL, Vn, Dn, 1, 0, 0, 0, 0);

    embed_k<<<(Mn * Dn) / 256, 256>>>(x, ce, pe);

    const int nD4 = Mn * Dn / 4;
    const int nF4 = Mn * FFn / 4;
    const int nS4 = BHn * Tn * Tn / 4;
    const long long SAB = (long long)Tn * Dn;
    const long long SS1 = (long long)Tn * Tn;
    const long long SVT = (long long)HSn * Tn;

    for (int l = 0; l < Ln; l++){
        ln_k<<<Mn, 256>>>(h, y, ln1_s + l*Dn, ln1_b + l*Dn);
        convA<<<(nD4 + 255)/256, 256>>>(y, yH, yL, nD4);

        gemm_mma<128><<<dim3(8,16,1), 256, SM128>>>(yH, yL, wqH + (size_t)l*DD, wqL + (size_t)l*DD,
            nullptr, nullptr, q, Dn, Dn, Dn, Dn, 1, 0,0,0,0,0,0, 0, 1.f);
        gemm_mma<128><<<dim3(8,16,1), 256, SM128>>>(yH, yL, wkH + (size_t)l*DD, wkL + (size_t)l*DD,
            nullptr, nullptr, k, Dn, Dn, Dn, Dn, 1, 0,0,0,0,0,0, 0, 1.f);
        gemm_mma<128><<<dim3(8,16,1), 256, SM128>>>(yH, yL, wvH + (size_t)l*DD, wvL + (size_t)l*DD,
            nullptr, nullptr, v, Dn, Dn, Dn, Dn, 1, 0,0,0,0,0,0, 0, 1.f);

        convA<<<(nD4 + 255)/256, 256>>>(q, qH, qL, nD4);
        convA<<<(nD4 + 255)/256, 256>>>(k, kH, kL, nD4);
        convT<<<dim3(HSn/32, Tn/32, BHn), cb>>>(v, vtH, vtL, Dn, Tn, Hn,
            SAB, (long long)HSn, (long long)Hn*SVT, SVT);

        gemm_mma<128><<<dim3(4,4,BHn), 256, SM128>>>(qH, qL, kH, kL, nullptr, nullptr, s,
            HSn, Dn, Dn, Tn, Hn, SAB, (long long)HSn, SAB, (long long)HSn,
            (long long)Hn*SS1, SS1, F_SCALE | F_CAUSAL, 0.125f);
        softmax_k<<<BHn*Tn, 128>>>();
        convA<<<(nS4 + 255)/256, 256>>>(s, sH, sL, nS4);

        gemm_mma<64><<<dim3(1,4,BHn), 256, SM64>>>(sH, sL, vtH, vtL, nullptr, nullptr, o,
            Tn, Tn, Tn, Dn, Hn, (long long)Hn*SS1, SS1, (long long)Hn*SVT, SVT,
            SAB, (long long)HSn, 0, 1.f);

        convA<<<(nD4 + 255)/256, 256>>>(o, oH, oL, nD4);
        gemm_mma<128><<<dim3(8,16,1), 256, SM128>>>(oH, oL, woH + (size_t)l*DD, woL + (size_t)l*DD,
            bo + l*Dn, h, h, Dn, Dn, Dn, Dn, 1, 0,0,0,0,0,0, F_BIAS | F_RES, 1.f);

        ln_k<<<Mn, 256>>>(h, y, ln2_s + l*Dn, ln2_b + l*Dn);
        convA<<<(nD4 + 255)/256, 256>>>(y, yH, yL, nD4);
        gemm_mma<128><<<dim3(32,16,1), 256, SM128>>>(yH, yL, w1H + (size_t)l*DF, w1L + (size_t)l*DF,
            b1 + l*FFn, nullptr, a, Dn, Dn, Dn, FFn, 1, 0,0,0,0,0,0, F_BIAS | F_RELU, 1.f);
        convA<<<(nF4 + 255)/256, 256>>>(a, aH, aL, nF4);
        gemm_mma<128><<<dim3(8,16,1), 256, SM128>>>(aH, aL, w2H + (size_t)l*DF, w2L + (size_t)l*DF,
            b2 + l*Dn, h, h, FFn, FFn, FFn, Dn, 1, 0,0,0,0,0,0, F_BIAS | F_RES, 1.f);
    }

    ln_k<<<Mn, 256>>>(h, y, lnf_s, lnf_b);
    convA<<<(nD4 + 255)/256, 256>>>(y, yH, yL, nD4);
    gemm_mma<128><<<dim3(Vn/128, 16, 1), 256, SM128>>>(yH, yL, wfH, wfL,
        bf, nullptr, (float*)d_out, Dn, Dn, Dn, Vn, 1, 0,0,0,0,0,0, F_BIAS, 1.f);
}